// round 1
// baseline (speedup 1.0000x reference)
#include <cuda_runtime.h>
#include <cuda_bf16.h>

// Problem constants (fixed shapes from reference):
//   B=1, N=1000, T=256, D=512, M=T+2=258, NUM=10
//   out row = 6*512 + 10 = 3082 floats
#define N_CAND 1000
#define T_DIM 256
#define D_DIM 512
#define M_DIM 258
#define NUMF 10
#define ROW_OUT (6 * D_DIM + NUMF)   // 3082

// One block per candidate. 256 threads: each thread copies one float2 per
// 512-float section (512/2/256 == 1). All section start offsets within the
// output row (0,512,1024,1536,2048,2560) are even, and the row stride 3082
// is even, so float2 addressing is always 8B-aligned.
__global__ __launch_bounds__(256) void feature_gather_kernel(
    const int* __restrict__ cand,        // [N,6]
    const float* __restrict__ num,       // [N,10]
    const float* __restrict__ blo,       // [N,T,D]
    const float* __restrict__ att,       // [N,M,D]
    float* __restrict__ out)             // [N,3082]
{
    const int n = blockIdx.x;
    const int t = threadIdx.x;           // 0..255

    // Broadcast loads of the 6 candidate indices (L1 broadcast, no conflict).
    const int* c = cand + n * 6;
    const int c0 = c[0], c1 = c[1], c2 = c[2], c3 = c[3], c4 = c[4], c5 = c[5];

    const float2* blo2 = (const float2*)(blo + (size_t)n * T_DIM * D_DIM);
    const float2* att2 = (const float2*)(att + (size_t)n * M_DIM * D_DIM);
    float2* out2 = (float2*)(out + (size_t)n * ROW_OUT);

    const int HD2 = D_DIM / 2; // 256 float2 per section == blockDim

    // Sections: g1=blo[c1], g2=blo[c2], g4=blo[c4], g5=blo[c5],
    //           parent=att[c0+2], child=att[c3+2]
    out2[0 * HD2 + t] = blo2[(size_t)c1 * HD2 + t];
    out2[1 * HD2 + t] = blo2[(size_t)c2 * HD2 + t];
    out2[2 * HD2 + t] = blo2[(size_t)c4 * HD2 + t];
    out2[3 * HD2 + t] = blo2[(size_t)c5 * HD2 + t];
    out2[4 * HD2 + t] = att2[(size_t)(c0 + 2) * HD2 + t];
    out2[5 * HD2 + t] = att2[(size_t)(c3 + 2) * HD2 + t];

    // Numeric features: 10 floats = 5 float2, threads 0..4.
    if (t < NUMF / 2) {
        const float2* num2 = (const float2*)(num + (size_t)n * NUMF);
        out2[6 * HD2 + t] = num2[t];
    }
}

extern "C" void kernel_launch(void* const* d_in, const int* in_sizes, int n_in,
                              void* d_out, int out_size) {
    const int*   cand = (const int*)d_in[0];
    const float* num  = (const float*)d_in[1];
    const float* blo  = (const float*)d_in[2];
    const float* att  = (const float*)d_in[3];
    float* out = (float*)d_out;

    feature_gather_kernel<<<N_CAND, 256>>>(cand, num, blo, att, out);
}